// round 14
// baseline (speedup 1.0000x reference)
#include <cuda_runtime.h>
#include <cuda_bf16.h>

// Accumulators in device globals (no allocation allowed). Zero-initialized at
// module load; the last block resets them to zero after producing the output,
// so every graph replay sees identical starting state (deterministic).
__device__ double       g_loc_sum = 0.0;
__device__ int          g_npos    = 0;
__device__ unsigned int g_ticket  = 0u;

#define GRID_BLOCKS 2368   // 16 CTA-waves worth of pressure on 148 SMs

// Branch-free smooth L1:  m = min(|d|,1);  m*(|d| - 0.5m)
//   |d|<1: m=|d| -> |d|^2 - 0.5|d|^2 = 0.5 d^2   (exact)
//   |d|>=1: m=1  -> |d| - 0.5                    (exact)
__device__ __forceinline__ float smooth_l1_f(float d) {
    float ad = fabsf(d);
    float m  = fminf(ad, 1.0f);
    return m * fmaf(-0.5f, m, ad);
}

__device__ __forceinline__ float anchor_loss(const float4* __restrict__ lp,
                                             const float4* __restrict__ lt,
                                             int a) {
    float4 p0 = lp[2 * a];
    float4 p1 = lp[2 * a + 1];
    float4 q0 = lt[2 * a];
    float4 q1 = lt[2 * a + 1];
    float s = smooth_l1_f(p0.x - q0.x);
    s += smooth_l1_f(p0.y - q0.y);
    s += smooth_l1_f(p0.z - q0.z);
    s += smooth_l1_f(p0.w - q0.w);
    s += smooth_l1_f(p1.x - q1.x);
    s += smooth_l1_f(p1.y - q1.y);
    s += smooth_l1_f(p1.z - q1.z);
    s += smooth_l1_f(p1.w - q1.w);
    return s;
}

// Round 2 finding: DRAM fetch granularity is effectively 128B (4 anchors per
// line), so predicating loads on t>0 saves <5% of traffic (random positives
// touch 93.75% of lines) while serializing LDG t -> branch -> LDG data each
// iteration. Load everything unconditionally, mask arithmetically, and unroll
// x2 so ptxas can front-batch ~9 independent loads per loop body (deeper MLP
// -> higher DRAM utilization; R2 measured only 72.9% DRAM-active).
__global__ void __launch_bounds__(256) ohem_reduce_kernel(
    const float4* __restrict__ loc_preds,    // [n_anchors*2] float4
    const float4* __restrict__ loc_targets,  // [n_anchors*2] float4
    const int*    __restrict__ cls_targets,  // [n_anchors]
    int n_anchors,
    float* __restrict__ out)
{
    float lsum = 0.0f;
    int   cnt  = 0;

    const int stride = gridDim.x * blockDim.x;
    int a = blockIdx.x * blockDim.x + threadIdx.x;

    // Unroll-2 main loop: both anchors' loads are independent.
    for (; a + stride < n_anchors; a += 2 * stride) {
        int b = a + stride;
        int t0 = cls_targets[a];
        int t1 = cls_targets[b];
        float s0 = anchor_loss(loc_preds, loc_targets, a);
        float s1 = anchor_loss(loc_preds, loc_targets, b);

        int p0 = (t0 > 0);
        int p1 = (t1 > 0);
        cnt += p0 + p1;
        lsum = fmaf((float)p0, s0, lsum);
        lsum = fmaf((float)p1, s1, lsum);
    }
    // Tail (at most one element per thread).
    if (a < n_anchors) {
        int t = cls_targets[a];
        float s = anchor_loss(loc_preds, loc_targets, a);
        int p = (t > 0);
        cnt += p;
        lsum = fmaf((float)p, s, lsum);
    }

    // Warp reduce
    #pragma unroll
    for (int off = 16; off > 0; off >>= 1) {
        lsum += __shfl_down_sync(0xFFFFFFFFu, lsum, off);
        cnt  += __shfl_down_sync(0xFFFFFFFFu, cnt,  off);
    }

    __shared__ float s_sum[8];
    __shared__ int   s_cnt[8];
    __shared__ bool  s_is_last;
    int wid = threadIdx.x >> 5;
    int lid = threadIdx.x & 31;
    if (lid == 0) { s_sum[wid] = lsum; s_cnt[wid] = cnt; }
    __syncthreads();

    if (wid == 0) {
        lsum = (lid < (blockDim.x >> 5)) ? s_sum[lid] : 0.0f;
        cnt  = (lid < (blockDim.x >> 5)) ? s_cnt[lid] : 0;
        #pragma unroll
        for (int off = 4; off > 0; off >>= 1) {
            lsum += __shfl_down_sync(0xFFFFFFFFu, lsum, off);
            cnt  += __shfl_down_sync(0xFFFFFFFFu, cnt,  off);
        }
        if (lid == 0) {
            atomicAdd(&g_loc_sum, (double)lsum);
            atomicAdd(&g_npos, cnt);
            __threadfence();
            unsigned int ticket = atomicAdd(&g_ticket, 1u);
            s_is_last = (ticket == gridDim.x - 1u);
        }
    }
    __syncthreads();

    // Last block to finish: finalize + reset globals for the next replay.
    if (s_is_last && threadIdx.x == 0) {
        // cls branch is exactly zero for NUM_CLASSES == 1:
        //   ce = logsumexp(single elem) - that elem == 0 exactly in IEEE fp,
        //   so cls_loss == 0 and the hard-negative mining is dead code.
        double n = (double)g_npos;
        out[0] = (n > 0.0) ? (float)(0.2 * g_loc_sum / n) : 0.0f;
        g_loc_sum = 0.0;
        g_npos    = 0;
        __threadfence();
        g_ticket  = 0u;
    }
}

extern "C" void kernel_launch(void* const* d_in, const int* in_sizes, int n_in,
                              void* d_out, int out_size)
{
    const float4* loc_preds   = (const float4*)d_in[0];
    const float4* loc_targets = (const float4*)d_in[1];
    // d_in[2] = cls_preds — provably unused (ce == 0 exactly for C == 1).
    const int*    cls_targets = (const int*)d_in[3];
    const int n_anchors = in_sizes[3];   // B * A = 3,200,000

    ohem_reduce_kernel<<<GRID_BLOCKS, 256>>>(loc_preds, loc_targets,
                                             cls_targets, n_anchors,
                                             (float*)d_out);
}